// round 1
// baseline (speedup 1.0000x reference)
#include <cuda_runtime.h>
#include <math.h>

#define DTC 0.001
#define Pdim 1024
#define Hdim 256
#define Ldim 16384

#define HT 128
#define LT 128
#define PC 16
#define NK (Pdim / PC)   // 64 stages

typedef unsigned long long u64;

// Scratch (allocation-free rule: __device__ globals)
__device__ float2 g_W[Pdim * Hdim];              // [p][h] complex, 2 MB
__device__ float2 g_V[(size_t)Pdim * Ldim];      // [p][l] complex, 128 MB

// ---------------------------------------------------------------------------
// packed f32x2 helpers (PTX-only path; ptxas never auto-fuses FFMA2)
// ---------------------------------------------------------------------------
__device__ __forceinline__ u64 pk2(float a, float b) {
    u64 r; asm("mov.b64 %0, {%1, %2};" : "=l"(r) : "f"(a), "f"(b)); return r;
}
__device__ __forceinline__ u64 f2(u64 a, u64 b, u64 c) {
    u64 d; asm("fma.rn.f32x2 %0, %1, %2, %3;" : "=l"(d) : "l"(a), "l"(b), "l"(c)); return d;
}

// ---------------------------------------------------------------------------
// Setup: W[h,p] = C[h,p] * ((A_bar[p]-1)/Ac[p]) * B[p,h]
// A_bar computed in fp64 then rounded (match reference's fp32 A_bar as closely
// as possible: everything downstream amplifies A_bar's ulps by up to L).
// ---------------------------------------------------------------------------
__global__ void setup_W(const float* __restrict__ A,
                        const float* __restrict__ B,
                        const float* __restrict__ C) {
    int idx = blockIdx.x * blockDim.x + threadIdx.x;   // over P*H
    if (idx >= Pdim * Hdim) return;
    int p = idx / Hdim, h = idx % Hdim;

    float ar = A[2 * p], ai = A[2 * p + 1];
    double e  = exp((double)ar * DTC);
    double th = (double)ai * DTC;
    float abr = (float)(e * cos(th));
    float abi = (float)(e * sin(th));

    // (A_bar - 1) / Ac  in fp32 (reference does this cancellation in fp32)
    float nr = abr - 1.0f, ni = abi;
    float den = ar * ar + ai * ai;
    float cr = (nr * ar + ni * ai) / den;
    float ci = (ni * ar - nr * ai) / den;

    float br = B[(p * Hdim + h) * 2], bi = B[(p * Hdim + h) * 2 + 1];
    float bbr = cr * br - ci * bi;
    float bbi = cr * bi + ci * br;

    float crr = C[(h * Pdim + p) * 2], cri = C[(h * Pdim + p) * 2 + 1];
    float wr = crr * bbr - cri * bbi;
    float wi = crr * bbi + cri * bbr;

    g_W[p * Hdim + h] = make_float2(wr, wi);
}

// ---------------------------------------------------------------------------
// V generation: V[p,l] = A_bar[p]^l = exp(l*log(A_bar)).
// One warp handles (p, 2048-l segment); lane d owns l = base+d, stepping by 32
// via fp64 complex recurrence with ratio A_bar^32 -> coalesced float2 stores.
// log(A_bar) taken in fp64 FROM THE ROUNDED fp32 A_bar (matches reference).
// ---------------------------------------------------------------------------
__global__ void gen_V(const float* __restrict__ A) {
    int wid  = blockIdx.x * (blockDim.x >> 5) + (threadIdx.x >> 5);  // 8192 warps
    int lane = threadIdx.x & 31;
    int p   = wid >> 3;
    int seg = wid & 7;

    float ar = A[2 * p], ai = A[2 * p + 1];
    double e  = exp((double)ar * DTC);
    double th = (double)ai * DTC;
    float abr = (float)(e * cos(th));
    float abi = (float)(e * sin(th));

    double lr = 0.5 * log((double)abr * (double)abr + (double)abi * (double)abi);
    double li = atan2((double)abi, (double)abr);

    int l0 = seg * 2048 + lane;
    double m = exp(lr * (double)l0);
    double a = li * (double)l0;
    double cr = m * cos(a), ci = m * sin(a);

    double sm = exp(lr * 32.0), sa = li * 32.0;
    double sr = sm * cos(sa), si = sm * sin(sa);

    float2* row = g_V + (size_t)p * Ldim;
    int l = l0;
    #pragma unroll 4
    for (int t = 0; t < 64; t++) {
        row[l] = make_float2((float)cr, (float)ci);
        double ncr = cr * sr - ci * si;
        double nci = cr * si + ci * sr;
        cr = ncr; ci = nci;
        l += 32;
    }
}

// ---------------------------------------------------------------------------
// Main GEMM: out[h,l] = sum_p W[h,p] * V[p,l]   (complex, fp32 via FFMA2)
// Block tile 128h x 128l, 256 threads, 8x8 complex micro-tile per thread.
// Complex MAC packed as (cr,ci) += (wr,wr)*(vr,vi) + (-wi,wi)*(vi,vr).
// Smem planes: W natural, V natural, V swapped (swap built during staging so
// the inner loop is pure LDS.128 + FFMA2 + 16 W-broadcast packs per p.
// ---------------------------------------------------------------------------
__global__ __launch_bounds__(256, 1)
void vand_gemm(float2* __restrict__ out) {
    __shared__ float4 sW [PC][HT / 2];   // 16 KB  (float4 = 2 complex)
    __shared__ float4 sV [PC][LT / 2];   // 16 KB  (vr,vi)
    __shared__ float4 sVs[PC][LT / 2];   // 16 KB  (vi,vr)

    const int tid = threadIdx.x;
    const int tx  = tid & 15;            // 16 l-groups
    const int ty  = tid >> 4;            // 16 h-groups
    const int l0  = blockIdx.x * LT;
    const int h0  = blockIdx.y * HT;

    u64 acc[8][8];
    #pragma unroll
    for (int j = 0; j < 8; j++)
        #pragma unroll
        for (int i = 0; i < 8; i++) acc[j][i] = 0ull;

    float4 rw[4], rv[4];
    // prefetch stage 0
    #pragma unroll
    for (int j = 0; j < 4; j++) {
        int f = tid + 256 * j, r = f >> 6, c = f & 63;
        rw[j] = *((const float4*)(g_W + (size_t)r * Hdim + h0) + c);
        rv[j] = *((const float4*)(g_V + (size_t)r * Ldim + l0) + c);
    }

    for (int k = 0; k < NK; k++) {
        // stage k: regs -> smem (build swapped V plane on the fly)
        #pragma unroll
        for (int j = 0; j < 4; j++) {
            int f = tid + 256 * j, r = f >> 6, c = f & 63;
            sW [r][c] = rw[j];
            sV [r][c] = rv[j];
            sVs[r][c] = make_float4(rv[j].y, rv[j].x, rv[j].w, rv[j].z);
        }
        __syncthreads();

        if (k + 1 < NK) {
            int p0 = (k + 1) * PC;
            #pragma unroll
            for (int j = 0; j < 4; j++) {
                int f = tid + 256 * j, r = f >> 6, c = f & 63;
                rw[j] = *((const float4*)(g_W + (size_t)(p0 + r) * Hdim + h0) + c);
                rv[j] = *((const float4*)(g_V + (size_t)(p0 + r) * Ldim + l0) + c);
            }
        }

        #pragma unroll 4
        for (int pp = 0; pp < PC; pp++) {
            u64 vn[8], vs[8];
            const ulonglong2* pV  = (const ulonglong2*)&sV [pp][0];
            const ulonglong2* pVs = (const ulonglong2*)&sVs[pp][0];
            ulonglong2 t;
            t = pV [tx * 2];          vn[0] = t.x; vn[1] = t.y;
            t = pV [tx * 2 + 1];      vn[2] = t.x; vn[3] = t.y;
            t = pV [32 + tx * 2];     vn[4] = t.x; vn[5] = t.y;
            t = pV [32 + tx * 2 + 1]; vn[6] = t.x; vn[7] = t.y;
            t = pVs[tx * 2];          vs[0] = t.x; vs[1] = t.y;
            t = pVs[tx * 2 + 1];      vs[2] = t.x; vs[3] = t.y;
            t = pVs[32 + tx * 2];     vs[4] = t.x; vs[5] = t.y;
            t = pVs[32 + tx * 2 + 1]; vs[6] = t.x; vs[7] = t.y;

            #pragma unroll
            for (int j2 = 0; j2 < 4; j2++) {
                float4 w = sW[pp][ty * 4 + j2];   // 2 complex W (broadcast)
                u64 a0 = pk2(w.x, w.x);
                u64 m0 = pk2(-w.y, w.y);
                u64 a1 = pk2(w.z, w.z);
                u64 m1 = pk2(-w.w, w.w);
                #pragma unroll
                for (int i = 0; i < 8; i++) {
                    acc[2 * j2    ][i] = f2(a0, vn[i], acc[2 * j2    ][i]);
                    acc[2 * j2    ][i] = f2(m0, vs[i], acc[2 * j2    ][i]);
                    acc[2 * j2 + 1][i] = f2(a1, vn[i], acc[2 * j2 + 1][i]);
                    acc[2 * j2 + 1][i] = f2(m1, vs[i], acc[2 * j2 + 1][i]);
                }
            }
        }
        __syncthreads();
    }

    // Epilogue: thread's 8 l = {tx*4..tx*4+3} and {64+tx*4..+3} -> two 32B
    // runs per h row, lanes adjacent -> fully coalesced 128-bit stores.
    #pragma unroll
    for (int j = 0; j < 8; j++) {
        int h = h0 + ty * 8 + j;
        float2* rowp = out + (size_t)h * Ldim + l0;
        *(ulonglong2*)&rowp[tx * 4]          = make_ulonglong2(acc[j][0], acc[j][1]);
        *(ulonglong2*)&rowp[tx * 4 + 2]      = make_ulonglong2(acc[j][2], acc[j][3]);
        *(ulonglong2*)&rowp[64 + tx * 4]     = make_ulonglong2(acc[j][4], acc[j][5]);
        *(ulonglong2*)&rowp[64 + tx * 4 + 2] = make_ulonglong2(acc[j][6], acc[j][7]);
    }
}

// ---------------------------------------------------------------------------
extern "C" void kernel_launch(void* const* d_in, const int* in_sizes, int n_in,
                              void* d_out, int out_size) {
    const float* A = (const float*)d_in[0];   // (P, 2)
    const float* B = (const float*)d_in[1];   // (P, H, 2)
    const float* C = (const float*)d_in[2];   // (H, P, 2)
    float2* out = (float2*)d_out;             // (H, L, 2) viewed as float2[H*L]

    setup_W<<<(Pdim * Hdim) / 256, 256>>>(A, B, C);
    gen_V<<<(Pdim * 8) / 8, 256>>>(A);        // 8192 warps / 8 warps-per-block
    vand_gemm<<<dim3(Ldim / LT, Hdim / HT), 256>>>(out);
}

// round 3
// speedup vs baseline: 3.0580x; 3.0580x over previous
#include <cuda_runtime.h>
#include <cuda_bf16.h>
#include <math.h>
#include <stdint.h>

#define DTC 0.001
#define Pdim 1024
#define Hdim 256
#define Ldim 16384
#define Ktot 2048      // 2*P
#define Ntot 32768     // 2*L
#define NKC  32        // K chunks of 64

// ---------------------------------------------------------------------------
// Device-global scratch (allocation-free rule)
// ---------------------------------------------------------------------------
__device__ __align__(16) float2  g_ab[Pdim];     // fp32 A_bar
__device__ __align__(16) float2  g_cf[Pdim];     // (A_bar-1)/Ac
__device__ __align__(16) double2 g_lg[Pdim];     // log(A_bar) fp64
// A matrices [kc(32)][m(256)][kk(64)] bf16  (1 MB each)
__device__ __align__(128) __nv_bfloat16 g_Ahi[(size_t)32 * 256 * 64];
__device__ __align__(128) __nv_bfloat16 g_Alo[(size_t)32 * 256 * 64];
// B matrices [kc(32)][n(32768)][kk(64)] bf16 (128 MB each)
__device__ __align__(128) __nv_bfloat16 g_Bhi[(size_t)32 * 32768 * 64];
__device__ __align__(128) __nv_bfloat16 g_Blo[(size_t)32 * 32768 * 64];

// ---------------------------------------------------------------------------
// helpers
// ---------------------------------------------------------------------------
__device__ __forceinline__ uint32_t s2u(const void* p) {
    uint32_t a;
    asm("{ .reg .u64 t; cvta.to.shared.u64 t, %1; cvt.u32.u64 %0, t; }"
        : "=r"(a) : "l"(p));
    return a;
}

__device__ __forceinline__ unsigned pack_bf(float lo, float hi) {
    unsigned r;
    asm("{\n\t.reg .b16 a, b;\n\tcvt.rn.bf16.f32 a, %1;\n\tcvt.rn.bf16.f32 b, %2;\n\t"
        "mov.b32 %0, {a, b};\n\t}" : "=r"(r) : "f"(lo), "f"(hi));
    return r;
}

__device__ __forceinline__ void cpa(uint32_t dst, const void* src) {
    asm volatile("cp.async.cg.shared.global [%0], [%1], 16;"
                 :: "r"(dst), "l"(src) : "memory");
}

__device__ __forceinline__ void ldm4(uint32_t* r, uint32_t a) {
    asm volatile("ldmatrix.sync.aligned.m8n8.x4.shared.b16 {%0,%1,%2,%3}, [%4];"
                 : "=r"(r[0]), "=r"(r[1]), "=r"(r[2]), "=r"(r[3]) : "r"(a));
}

__device__ __forceinline__ void mma16816(float* d, const uint32_t* a,
                                         uint32_t b0, uint32_t b1) {
    asm volatile(
        "mma.sync.aligned.m16n8k16.row.col.f32.bf16.bf16.f32 "
        "{%0,%1,%2,%3}, {%4,%5,%6,%7}, {%8,%9}, {%0,%1,%2,%3};"
        : "+f"(d[0]), "+f"(d[1]), "+f"(d[2]), "+f"(d[3])
        : "r"(a[0]), "r"(a[1]), "r"(a[2]), "r"(a[3]), "r"(b0), "r"(b1));
}

// ---------------------------------------------------------------------------
// k_pre: per-p constants (fp64 transcendentals once per p)
// ---------------------------------------------------------------------------
__global__ void k_pre(const float* __restrict__ A) {
    int p = blockIdx.x * blockDim.x + threadIdx.x;
    if (p >= Pdim) return;
    float ar = A[2 * p], ai = A[2 * p + 1];
    double e = exp((double)ar * DTC), th = (double)ai * DTC;
    float abr = (float)(e * cos(th));
    float abi = (float)(e * sin(th));
    float nr = abr - 1.0f, ni = abi;
    float den = ar * ar + ai * ai;
    g_ab[p] = make_float2(abr, abi);
    g_cf[p] = make_float2((nr * ar + ni * ai) / den, (ni * ar - nr * ai) / den);
    g_lg[p] = make_double2(0.5 * log((double)abr * abr + (double)abi * abi),
                           atan2((double)abi, (double)abr));
}

// ---------------------------------------------------------------------------
// k_setupA: W[h,p] = C[h,p]*coef[p]*B[p,h]; packed-real, split bf16 hi/lo.
// Layout [kc][m=h][kk=64], A[h][2p]=Wr, A[h][2p+1]=Wi.
// ---------------------------------------------------------------------------
__global__ void k_setupA(const float* __restrict__ B, const float* __restrict__ C) {
    int idx = blockIdx.x * 256 + threadIdx.x;     // over P*H
    int p = idx & (Pdim - 1), h = idx >> 10;
    float2 cf = g_cf[p];
    float br = B[(p * Hdim + h) * 2], bi = B[(p * Hdim + h) * 2 + 1];
    float bbr = cf.x * br - cf.y * bi;
    float bbi = cf.x * bi + cf.y * br;
    float cr = C[(h * Pdim + p) * 2], ci = C[(h * Pdim + p) * 2 + 1];
    float wr = cr * bbr - ci * bbi;
    float wi = cr * bbi + ci * bbr;
    float wrh = __bfloat162float(__float2bfloat16_rn(wr));
    float wih = __bfloat162float(__float2bfloat16_rn(wi));
    size_t o = ((size_t)(p >> 5) * 256 + h) * 32 + (p & 31);
    ((unsigned*)g_Ahi)[o] = pack_bf(wr, wi);
    ((unsigned*)g_Alo)[o] = pack_bf(wr - wrh, wi - wih);
}

// ---------------------------------------------------------------------------
// k_genB: V[p,l] via fp32 recurrence (seeded fp64 every 128 l), written as
// packed-real bf16 hi/lo B matrices. Lanes own consecutive p -> coalesced.
// ---------------------------------------------------------------------------
__global__ void k_genB() {
    int wid = blockIdx.x * 8 + (threadIdx.x >> 5);   // 4096 warps
    int lane = threadIdx.x & 31;
    int pg = wid & 31, seg = wid >> 5;               // seg 0..127
    int p = pg * 32 + lane;

    float2 ab = g_ab[p];
    double2 lg = g_lg[p];
    int l0 = seg * 128;
    double m = exp(lg.x * (double)l0), a = lg.y * (double)l0;
    float vr = (float)(m * cos(a));
    float vi = (float)(m * sin(a));

    unsigned* bh = (unsigned*)g_Bhi;
    unsigned* bl = (unsigned*)g_Blo;
    size_t rowbase = (size_t)pg * 32768 * 32 + lane;  // u32 units

    #pragma unroll 4
    for (int t = 0; t < 128; t++) {
        int l = l0 + t;
        float vrh = __bfloat162float(__float2bfloat16_rn(vr));
        float vih = __bfloat162float(__float2bfloat16_rn(vi));
        size_t o0 = rowbase + (size_t)(2 * l) * 32;
        bh[o0]      = pack_bf(vr, -vi);          // row n=2l   : (Vr, -Vi)
        bh[o0 + 32] = pack_bf(vi, vr);           // row n=2l+1 : (Vi,  Vr)
        bl[o0]      = pack_bf(vr - vrh, -(vi - vih));
        bl[o0 + 32] = pack_bf(vi - vih, vr - vrh);
        float nvr = vr * ab.x - vi * ab.y;
        float nvi = vr * ab.y + vi * ab.x;
        vr = nvr; vi = nvi;
    }
}

// ---------------------------------------------------------------------------
// k_gemm: HMMA mma.sync bf16, CTA tile 128m x 128n, 512 thr (16 warps 4x4,
// warp tile 32x32), K chunks of 64, 2-stage cp.async pipeline (128 KB smem).
// 3 products per chunk: Ahi*Bhi + Ahi*Blo + Alo*Bhi into fp32 acc.
// Stage layout: [Ahi 16K][Alo 16K][Bhi 16K][Blo 16K] = 64K per stage.
// ---------------------------------------------------------------------------
__global__ __launch_bounds__(512, 1) void k_gemm(float* __restrict__ out) {
    extern __shared__ char smp[];
    const int tid  = threadIdx.x;
    const int lane = tid & 31;
    const int wid  = tid >> 5;
    const int wm   = wid >> 2;            // 0..3
    const int wn   = wid & 3;             // 0..3
    const int m0   = blockIdx.x * 128;
    const int n0   = blockIdx.y * 128;
    const uint32_t sb = s2u(smp);

    float acc[2][4][4];
    #pragma unroll
    for (int i = 0; i < 2; i++)
        #pragma unroll
        for (int j = 0; j < 4; j++)
            #pragma unroll
            for (int t = 0; t < 4; t++) acc[i][j][t] = 0.0f;

    // cp.async staging mapping: thread covers 2 (row,col) slots per plane.
    const int crow = tid >> 3;            // 0..63 (+64 on second iter)
    const int ccol = tid & 7;             // 16B column

    // ---- issue chunk kc into stage s ----
    auto issue = [&](int kc, int s) {
        uint32_t st = sb + s * 65536;
        #pragma unroll
        for (int i = 0; i < 2; i++) {
            int row = crow + 64 * i;
            uint32_t d = st + row * 128 + ((ccol ^ (row & 7)) << 4);
            size_t oA = ((size_t)kc * 256 + m0 + row) * 64 + ccol * 8;
            cpa(d,         g_Ahi + oA);
            cpa(d + 16384, g_Alo + oA);
            size_t oB = ((size_t)kc * 32768 + n0 + row) * 64 + ccol * 8;
            cpa(d + 32768, g_Bhi + oB);
            cpa(d + 49152, g_Blo + oB);
        }
        asm volatile("cp.async.commit_group;" ::: "memory");
    };

    // ldmatrix per-lane row bases
    const int r15 = lane & 15, h16 = lane >> 4;
    const int rA0 = wm * 32 + r15, rA1 = rA0 + 16;
    const int rB0 = wn * 32 + r15, rB1 = rB0 + 16;

    issue(0, 0);

    for (int k = 0; k < NKC; k++) {
        const int s = k & 1;
        if (k + 1 < NKC) {
            issue(k + 1, s ^ 1);
            asm volatile("cp.async.wait_group 1;" ::: "memory");
        } else {
            asm volatile("cp.async.wait_group 0;" ::: "memory");
        }
        __syncthreads();

        const uint32_t sA = sb + s * 65536;
        const uint32_t sB = sA + 32768;

        #pragma unroll
        for (int ks = 0; ks < 4; ks++) {
            const int cc = 2 * ks + h16;
            uint32_t a0[4], a1[4], bh0[4], bh1[4], bl0[4], bl1[4];
            uint32_t oA0 = rA0 * 128 + ((cc ^ (rA0 & 7)) << 4);
            uint32_t oA1 = rA1 * 128 + ((cc ^ (rA1 & 7)) << 4);
            uint32_t oB0 = rB0 * 128 + ((cc ^ (rB0 & 7)) << 4);
            uint32_t oB1 = rB1 * 128 + ((cc ^ (rB1 & 7)) << 4);

            ldm4(a0,  sA + oA0);
            ldm4(a1,  sA + oA1);
            ldm4(bh0, sB + oB0);
            ldm4(bh1, sB + oB1);
            ldm4(bl0, sB + 16384 + oB0);
            ldm4(bl1, sB + 16384 + oB1);

            // hi*hi
            mma16816(acc[0][0], a0, bh0[0], bh0[2]);
            mma16816(acc[0][1], a0, bh0[1], bh0[3]);
            mma16816(acc[0][2], a0, bh1[0], bh1[2]);
            mma16816(acc[0][3], a0, bh1[1], bh1[3]);
            mma16816(acc[1][0], a1, bh0[0], bh0[2]);
            mma16816(acc[1][1], a1, bh0[1], bh0[3]);
            mma16816(acc[1][2], a1, bh1[0], bh1[2]);
            mma16816(acc[1][3], a1, bh1[1], bh1[3]);
            // hi*lo
            mma16816(acc[0][0], a0, bl0[0], bl0[2]);
            mma16816(acc[0][1], a0, bl0[1], bl0[3]);
            mma16816(acc[0][2], a0, bl1[0], bl1[2]);
            mma16816(acc[0][3], a0, bl1[1], bl1[3]);
            mma16816(acc[1][0], a1, bl0[0], bl0[2]);
            mma16816(acc[1][1], a1, bl0[1], bl0[3]);
            mma16816(acc[1][2], a1, bl1[0], bl1[2]);
            mma16816(acc[1][3], a1, bl1[1], bl1[3]);
            // lo*hi (reload A frags from lo plane)
            ldm4(a0, sA + 16384 + oA0);
            ldm4(a1, sA + 16384 + oA1);
            mma16816(acc[0][0], a0, bh0[0], bh0[2]);
            mma16816(acc[0][1], a0, bh0[1], bh0[3]);
            mma16816(acc[0][2], a0, bh1[0], bh1[2]);
            mma16816(acc[0][3], a0, bh1[1], bh1[3]);
            mma16816(acc[1][0], a1, bh0[0], bh0[2]);
            mma16816(acc[1][1], a1, bh0[1], bh0[3]);
            mma16816(acc[1][2], a1, bh1[0], bh1[2]);
            mma16816(acc[1][3], a1, bh1[1], bh1[3]);
        }
        __syncthreads();
    }

    // Epilogue: acc[im][jn] covers (m = wm*32+im*16+lane/4 (+8), n = wn*32+jn*8+(lane%4)*2)
    const int mrow = lane >> 2, ncol = (lane & 3) * 2;
    #pragma unroll
    for (int im = 0; im < 2; im++) {
        int m = m0 + wm * 32 + im * 16 + mrow;
        #pragma unroll
        for (int jn = 0; jn < 4; jn++) {
            int n = n0 + wn * 32 + jn * 8 + ncol;
            float* p = out + (size_t)m * Ntot + n;
            *(float2*)p = make_float2(acc[im][jn][0], acc[im][jn][1]);
            *(float2*)(p + (size_t)8 * Ntot) = make_float2(acc[im][jn][2], acc[im][jn][3]);
        }
    }
}

// ---------------------------------------------------------------------------
extern "C" void kernel_launch(void* const* d_in, const int* in_sizes, int n_in,
                              void* d_out, int out_size) {
    const float* A = (const float*)d_in[0];
    const float* B = (const float*)d_in[1];
    const float* C = (const float*)d_in[2];
    float* out = (float*)d_out;

    cudaFuncSetAttribute(k_gemm, cudaFuncAttributeMaxDynamicSharedMemorySize, 131072);

    k_pre<<<4, 256>>>(A);
    k_setupA<<<1024, 256>>>(B, C);
    k_genB<<<512, 256>>>();
    k_gemm<<<dim3(2, 256), 512, 131072>>>(out);
}